// round 10
// baseline (speedup 1.0000x reference)
#include <cuda_runtime.h>
#include <cstdint>

// Problem constants
#define E_DIM   1024
#define H_NUM   16
#define B_NUM   4
#define S_LEN   2048
#define R_RANK  8
#define M_TOK   (B_NUM * S_LEN)      // 8192
#define N_QKV   (3 * E_DIM)          // 3072
#define LORA_SCALING 2.0f
#define ATTN_SCALE   0.125f          // D^-0.5

// ---------------------------------------------------------------------------
// Scratch (device globals: allocation-free per harness rules)
// ---------------------------------------------------------------------------
__device__ float g_x[(size_t)M_TOK * E_DIM];     // tf32-rounded x    (32 MB)
__device__ float g_Wqkv[N_QKV * E_DIM];          // fused QKV weight  (12 MB)
__device__ float g_Wproj[E_DIM * E_DIM];         // fused proj weight (4 MB)
__device__ float g_qkv[(size_t)M_TOK * N_QKV];   // qkv activations (96 MB)
__device__ float g_att[(size_t)M_TOK * E_DIM];   // attention out   (32 MB)

// ---------------------------------------------------------------------------
// helpers
// ---------------------------------------------------------------------------
__device__ __forceinline__ uint32_t f2tf32(float f) {
    uint32_t o;
    asm("cvt.rna.tf32.f32 %0, %1;" : "=r"(o) : "f"(f));
    return o;
}
__device__ __forceinline__ float rndtf(float f) {
    return __uint_as_float(f2tf32(f));
}
__device__ __forceinline__ void mma_tf32(float& c0, float& c1, float& c2, float& c3,
                                         uint32_t a0, uint32_t a1, uint32_t a2, uint32_t a3,
                                         uint32_t b0, uint32_t b1) {
    asm volatile(
        "mma.sync.aligned.m16n8k8.row.col.f32.tf32.tf32.f32 "
        "{%0,%1,%2,%3}, {%4,%5,%6,%7}, {%8,%9}, {%0,%1,%2,%3};"
        : "+f"(c0), "+f"(c1), "+f"(c2), "+f"(c3)
        : "r"(a0), "r"(a1), "r"(a2), "r"(a3), "r"(b0), "r"(b1));
}
__device__ __forceinline__ void ldsm_x4(uint32_t& r0, uint32_t& r1,
                                        uint32_t& r2, uint32_t& r3, uint32_t addr) {
    asm volatile("ldmatrix.sync.aligned.m8n8.x4.shared.b16 {%0,%1,%2,%3}, [%4];"
                 : "=r"(r0), "=r"(r1), "=r"(r2), "=r"(r3) : "r"(addr));
}

// ---------------------------------------------------------------------------
// Kernel 0: round a tensor to tf32 (rna) once
// ---------------------------------------------------------------------------
__global__ void round_tf32(const float4* __restrict__ in, float4* __restrict__ out, int n4)
{
    int i = blockIdx.x * 256 + threadIdx.x;
    if (i >= n4) return;
    float4 v = in[i];
    v.x = rndtf(v.x); v.y = rndtf(v.y); v.z = rndtf(v.z); v.w = rndtf(v.w);
    out[i] = v;
}

// ---------------------------------------------------------------------------
// Kernel 1: fold LoRA into dense weight:  out = rna(W + 2 * (Bm @ Am))
// ---------------------------------------------------------------------------
__global__ void fuse_w(const float* __restrict__ W, const float* __restrict__ Am,
                       const float* __restrict__ Bm, float* __restrict__ out,
                       int Nrows)
{
    int idx = blockIdx.x * 256 + threadIdx.x;
    if (idx >= Nrows * 1024) return;
    int n = idx >> 10;
    int k = idx & 1023;
    float acc = W[idx];
#pragma unroll
    for (int r = 0; r < R_RANK; r++)
        acc = fmaf(LORA_SCALING * Bm[n * R_RANK + r], Am[r * 1024 + k], acc);
    out[idx] = rndtf(acc);
}

// ---------------------------------------------------------------------------
// tf32 tensor-core GEMM:  C[M,N] = A[M,K] @ W[N,K]^T (+ bias)
//   block tile 128x256, BK=16; 256 threads (8 warps: 2x4, 64x64 per warp)
//   inputs pre-rounded tf32 -> raw float4 STS; fragments via ldmatrix.x4
// ---------------------------------------------------------------------------
#define GSM_A   (128 * 20)                         // floats per A stage
#define GSM_B   (256 * 20)                         // floats per B stage
#define GEMM_SMEM_BYTES ((2 * GSM_A + 2 * GSM_B) * 4)   // 61440

template <bool BIAS, bool ROUND>
__global__ __launch_bounds__(256)
void gemm_mma(const float* __restrict__ A, const float* __restrict__ W,
              const float* __restrict__ bias, float* __restrict__ C,
              int Kn, int Nn)
{
    extern __shared__ float sgm[];
    float* Asm[2] = { sgm,            sgm + GSM_A };
    float* Wsm[2] = { sgm + 2*GSM_A,  sgm + 2*GSM_A + GSM_B };

    const int t    = threadIdx.x;
    const int wid  = t >> 5;
    const int lid  = t & 31;
    const int gid  = lid >> 2;
    const int tg   = lid & 3;
    const int wm   = (wid >> 2) * 64;       // 0 or 64
    const int wn   = (wid & 3) * 64;        // 0..192
    const int row0 = blockIdx.y << 7;
    const int col0 = blockIdx.x << 8;

    // ldmatrix lane addressing
    const int mh = lid >> 3;          // matrix id 0..3
    const int rr = lid & 7;
    const uint32_t Asm_sh = (uint32_t)__cvta_generic_to_shared(sgm);
    const uint32_t Wsm_sh = Asm_sh + 2 * GSM_A * 4;
    const uint32_t a_lane = ((((mh & 1) * 8 + rr) * 20 + (mh >> 1) * 4) << 2);
    const uint32_t b_lane = ((((mh >> 1) * 8 + rr) * 20 + (mh & 1) * 4) << 2);

    const int lr = t >> 2;            // 0..63
    const int lk = (t & 3) << 2;      // 0,4,8,12
    const float* Ap = A + (size_t)(row0 + lr) * Kn + lk;
    const float* Wp = W + (size_t)(col0 + lr) * Kn + lk;

    float acc[4][8][4];
#pragma unroll
    for (int i = 0; i < 4; i++)
#pragma unroll
        for (int j = 0; j < 8; j++)
#pragma unroll
            for (int r = 0; r < 4; r++) acc[i][j][r] = 0.0f;

    const int nkt = Kn >> 4;

    // preload stage 0
    {
#pragma unroll
        for (int p = 0; p < 2; p++)
            *(float4*)&Asm[0][(lr + p * 64) * 20 + lk] =
                *(const float4*)(Ap + (size_t)(p * 64) * Kn);
#pragma unroll
        for (int p = 0; p < 4; p++)
            *(float4*)&Wsm[0][(lr + p * 64) * 20 + lk] =
                *(const float4*)(Wp + (size_t)(p * 64) * Kn);
    }
    __syncthreads();

    for (int kt = 0; kt < nkt; kt++) {
        const int cur = kt & 1, nxt = cur ^ 1;

        float4 pa[2], pw[4];
        if (kt + 1 < nkt) {
            const int k0 = (kt + 1) << 4;
#pragma unroll
            for (int p = 0; p < 2; p++)
                pa[p] = *(const float4*)(Ap + (size_t)(p * 64) * Kn + k0);
#pragma unroll
            for (int p = 0; p < 4; p++)
                pw[p] = *(const float4*)(Wp + (size_t)(p * 64) * Kn + k0);
        }

#pragma unroll
        for (int kc = 0; kc < 16; kc += 8) {
            uint32_t af[4][4], bf[8][2];
#pragma unroll
            for (int mt = 0; mt < 4; mt++)
                ldsm_x4(af[mt][0], af[mt][1], af[mt][2], af[mt][3],
                        Asm_sh + ((((cur * 128 + wm + mt * 16) * 20) + kc) << 2) + a_lane);
#pragma unroll
            for (int p = 0; p < 4; p++)
                ldsm_x4(bf[2*p][0], bf[2*p][1], bf[2*p+1][0], bf[2*p+1][1],
                        Wsm_sh + ((((cur * 256 + wn + p * 16) * 20) + kc) << 2) + b_lane);
#pragma unroll
            for (int mt = 0; mt < 4; mt++)
#pragma unroll
                for (int nt = 0; nt < 8; nt++)
                    mma_tf32(acc[mt][nt][0], acc[mt][nt][1],
                             acc[mt][nt][2], acc[mt][nt][3],
                             af[mt][0], af[mt][1], af[mt][2], af[mt][3],
                             bf[nt][0], bf[nt][1]);
        }

        if (kt + 1 < nkt) {
#pragma unroll
            for (int p = 0; p < 2; p++)
                *(float4*)&Asm[nxt][(lr + p * 64) * 20 + lk] = pa[p];
#pragma unroll
            for (int p = 0; p < 4; p++)
                *(float4*)&Wsm[nxt][(lr + p * 64) * 20 + lk] = pw[p];
        }
        __syncthreads();
    }

#pragma unroll
    for (int mt = 0; mt < 4; mt++) {
        const int r = row0 + wm + mt * 16 + gid;
#pragma unroll
        for (int nt = 0; nt < 8; nt++) {
            const int c = col0 + wn + nt * 8 + tg * 2;
            float2 v0, v1;
            v0.x = acc[mt][nt][0]; v0.y = acc[mt][nt][1];
            v1.x = acc[mt][nt][2]; v1.y = acc[mt][nt][3];
            if (BIAS) {
                float b0 = bias[c], b1 = bias[c + 1];
                v0.x += b0; v0.y += b1;
                v1.x += b0; v1.y += b1;
            }
            if (ROUND) {
                v0.x = rndtf(v0.x); v0.y = rndtf(v0.y);
                v1.x = rndtf(v1.x); v1.y = rndtf(v1.y);
            }
            *(float2*)(&C[(size_t)r * Nn + c])       = v0;
            *(float2*)(&C[(size_t)(r + 8) * Nn + c]) = v1;
        }
    }
}

// ---------------------------------------------------------------------------
// Kernel 3: causal flash attention on tensor cores (tf32 mma, fp32 softmax)
// ---------------------------------------------------------------------------
#define QP_STR 68
#define KV_STR 68
#define ATTN2_SMEM_BYTES ((128*QP_STR*2 + 64*KV_STR*2) * 4)   // 104448

__global__ __launch_bounds__(128)
void attn_mma(const float* __restrict__ qkv, float* __restrict__ out)
{
    extern __shared__ uint32_t smu[];
    uint32_t* Qs = smu;                      // [128][QP_STR]
    uint32_t* Ps = Qs + 128 * QP_STR;        // [128][QP_STR]
    uint32_t* Ks = Ps + 128 * QP_STR;        // [64][KV_STR]  (k,d) natural
    uint32_t* Vt = Ks + 64 * KV_STR;         // [64][KV_STR]  (d,k) swizzled

    const int t   = threadIdx.x;
    const int w   = t >> 5;                  // 0..3
    const int lid = t & 31;
    const int gid = lid >> 2;
    const int tg  = lid & 3;

    const int mh = lid >> 3;
    const int rr = lid & 7;
    const uint32_t Qs_sh = (uint32_t)__cvta_generic_to_shared(Qs);
    const uint32_t Ps_sh = (uint32_t)__cvta_generic_to_shared(Ps);
    const uint32_t Ks_sh = (uint32_t)__cvta_generic_to_shared(Ks);
    const uint32_t Vt_sh = (uint32_t)__cvta_generic_to_shared(Vt);
    const uint32_t qp_lane = ((((mh & 1) * 8 + rr) * QP_STR + (mh >> 1) * 4) << 2);
    const uint32_t kb_lane = ((((mh >> 1) * 8 + rr) * KV_STR + (mh & 1) * 4) << 2);
    const int rbv = (mh >> 1) * 8 + rr;
    const int cbv = (mh & 1) * 4;

    const int qi = (int)gridDim.x - 1 - (int)blockIdx.x;  // long blocks first
    const int bh = blockIdx.y;
    const int b  = bh >> 4;
    const int h  = bh & 15;

    const float* qbase = qkv + (size_t)b * S_LEN * 3072 + h * 64;
    const float* kbase = qbase + 1024;
    const float* vbase = qbase + 2048;

    const int lr = t >> 4;            // 0..7
    const int dd = (t & 15) * 4;      // 0..60
    const int vq = (dd >> 3) & 3;

    {
        const float* qp = qbase + (size_t)(qi * 128 + lr) * 3072 + dd;
#pragma unroll
        for (int p = 0; p < 16; p++) {
            int r = lr + p * 8;
            float4 q4 = *(const float4*)(qp + (size_t)(p * 8) * 3072);
            uint4 u;
            u.x = __float_as_uint(q4.x * ATTN_SCALE);
            u.y = __float_as_uint(q4.y * ATTN_SCALE);
            u.z = __float_as_uint(q4.z * ATTN_SCALE);
            u.w = __float_as_uint(q4.w * ATTN_SCALE);
            *(uint4*)&Qs[r * QP_STR + dd] = u;
        }
    }

    const int R0 = w * 32 + gid;
    float O[2][8][4];
    float rmax[2][2], rsum[2][2];
#pragma unroll
    for (int mt = 0; mt < 2; mt++) {
        rmax[mt][0] = -1e30f; rmax[mt][1] = -1e30f;
        rsum[mt][0] = 0.0f;   rsum[mt][1] = 0.0f;
#pragma unroll
        for (int nt = 0; nt < 8; nt++)
#pragma unroll
            for (int r = 0; r < 4; r++) O[mt][nt][r] = 0.0f;
    }

    const int jmax = 2 * qi + 1;
    for (int j = 0; j <= jmax; j++) {
        __syncthreads();

        const float* kp = kbase + (size_t)(j * 64 + lr) * 3072 + dd;
        const float* vp = vbase + (size_t)(j * 64 + lr) * 3072 + dd;
#pragma unroll
        for (int p = 0; p < 8; p++) {
            int r = lr + p * 8;
            float4 k4 = *(const float4*)(kp + (size_t)(p * 8) * 3072);
            uint4 uk;
            uk.x = __float_as_uint(k4.x); uk.y = __float_as_uint(k4.y);
            uk.z = __float_as_uint(k4.z); uk.w = __float_as_uint(k4.w);
            *(uint4*)&Ks[r * KV_STR + dd] = uk;
            float4 v4 = *(const float4*)(vp + (size_t)(p * 8) * 3072);
            const int wcol = (((r >> 3) ^ vq) << 3) + (r & 7);
            Vt[(dd + 0) * KV_STR + wcol] = __float_as_uint(v4.x);
            Vt[(dd + 1) * KV_STR + wcol] = __float_as_uint(v4.y);
            Vt[(dd + 2) * KV_STR + wcol] = __float_as_uint(v4.z);
            Vt[(dd + 3) * KV_STR + wcol] = __float_as_uint(v4.w);
        }
        __syncthreads();

        if (j * 64 > qi * 128 + w * 32 + 31) continue;

        float sacc[2][8][4];
#pragma unroll
        for (int mt = 0; mt < 2; mt++)
#pragma unroll
            for (int nt = 0; nt < 8; nt++)
#pragma unroll
                for (int r = 0; r < 4; r++) sacc[mt][nt][r] = 0.0f;

#pragma unroll
        for (int kk = 0; kk < 8; kk++) {
            const int kb = kk * 8;
            uint32_t a[2][4], bk[8][2];
#pragma unroll
            for (int mt = 0; mt < 2; mt++)
                ldsm_x4(a[mt][0], a[mt][1], a[mt][2], a[mt][3],
                        Qs_sh + ((((w * 32 + mt * 16) * QP_STR) + kb) << 2) + qp_lane);
#pragma unroll
            for (int p = 0; p < 4; p++)
                ldsm_x4(bk[2*p][0], bk[2*p][1], bk[2*p+1][0], bk[2*p+1][1],
                        Ks_sh + ((((p * 16) * KV_STR) + kb) << 2) + kb_lane);
#pragma unroll
            for (int nt = 0; nt < 8; nt++) {
                mma_tf32(sacc[0][nt][0], sacc[0][nt][1], sacc[0][nt][2], sacc[0][nt][3],
                         a[0][0], a[0][1], a[0][2], a[0][3], bk[nt][0], bk[nt][1]);
                mma_tf32(sacc[1][nt][0], sacc[1][nt][1], sacc[1][nt][2], sacc[1][nt][3],
                         a[1][0], a[1][1], a[1][2], a[1][3], bk[nt][0], bk[nt][1]);
            }
        }

        if (j * 64 + 63 > qi * 128 + w * 32) {
#pragma unroll
            for (int mt = 0; mt < 2; mt++) {
                const int rg0 = qi * 128 + R0 + mt * 16;
                const int rg1 = rg0 + 8;
#pragma unroll
                for (int nt = 0; nt < 8; nt++) {
                    const int cg = j * 64 + nt * 8 + 2 * tg;
                    if (cg     > rg0) sacc[mt][nt][0] = -1e30f;
                    if (cg + 1 > rg0) sacc[mt][nt][1] = -1e30f;
                    if (cg     > rg1) sacc[mt][nt][2] = -1e30f;
                    if (cg + 1 > rg1) sacc[mt][nt][3] = -1e30f;
                }
            }
        }

#pragma unroll
        for (int mt = 0; mt < 2; mt++)
#pragma unroll
            for (int hf = 0; hf < 2; hf++) {
                const int i0 = hf * 2, i1 = hf * 2 + 1;
                float m = -1e30f;
#pragma unroll
                for (int nt = 0; nt < 8; nt++)
                    m = fmaxf(m, fmaxf(sacc[mt][nt][i0], sacc[mt][nt][i1]));
                m = fmaxf(m, __shfl_xor_sync(0xffffffffu, m, 1));
                m = fmaxf(m, __shfl_xor_sync(0xffffffffu, m, 2));

                float nm = fmaxf(rmax[mt][hf], m);
                float corr = __expf(rmax[mt][hf] - nm);
                rmax[mt][hf] = nm;

                const int prow = R0 + mt * 16 + hf * 8;
                float ls = 0.0f;
#pragma unroll
                for (int nt = 0; nt < 8; nt++) {
                    float p0 = __expf(sacc[mt][nt][i0] - nm);
                    float p1 = __expf(sacc[mt][nt][i1] - nm);
                    ls += p0 + p1;
                    uint32_t* d = &Ps[prow * QP_STR + nt * 8 + 2 * tg];
                    d[0] = f2tf32(p0); d[1] = f2tf32(p1);
                }
                ls += __shfl_xor_sync(0xffffffffu, ls, 1);
                ls += __shfl_xor_sync(0xffffffffu, ls, 2);
                rsum[mt][hf] = rsum[mt][hf] * corr + ls;

#pragma unroll
                for (int nt = 0; nt < 8; nt++) {
                    O[mt][nt][i0] *= corr;
                    O[mt][nt][i1] *= corr;
                }
            }
        __syncwarp();

#pragma unroll
        for (int kk = 0; kk < 8; kk++) {
            const int kb = kk * 8;
            uint32_t a[2][4], bv[8][2];
#pragma unroll
            for (int mt = 0; mt < 2; mt++)
                ldsm_x4(a[mt][0], a[mt][1], a[mt][2], a[mt][3],
                        Ps_sh + ((((w * 32 + mt * 16) * QP_STR) + kb) << 2) + qp_lane);
#pragma unroll
            for (int p = 0; p < 4; p++) {
                const int R  = p * 16 + rbv;
                const int Rq = (p * 2 + (mh >> 1)) & 3;
                const uint32_t addr =
                    Vt_sh + ((R * KV_STR + ((kk ^ Rq) << 3) + cbv) << 2);
                ldsm_x4(bv[2*p][0], bv[2*p][1], bv[2*p+1][0], bv[2*p+1][1], addr);
            }
#pragma unroll
            for (int nt = 0; nt < 8; nt++) {
                mma_tf32(O[0][nt][0], O[0][nt][1], O[0][nt][2], O[0][nt][3],
                         a[0][0], a[0][1], a[0][2], a[0][3], bv[nt][0], bv[nt][1]);
                mma_tf32(O[1][nt][0], O[1][nt][1], O[1][nt][2], O[1][nt][3],
                         a[1][0], a[1][1], a[1][2], a[1][3], bv[nt][0], bv[nt][1]);
            }
        }
    }

    float* obase = out + ((size_t)b * S_LEN + qi * 128) * 1024 + h * 64;
#pragma unroll
    for (int mt = 0; mt < 2; mt++) {
        const float inv0 = 1.0f / rsum[mt][0];
        const float inv1 = 1.0f / rsum[mt][1];
        const int r = R0 + mt * 16;
#pragma unroll
        for (int nt = 0; nt < 8; nt++) {
            const int c = nt * 8 + 2 * tg;
            float2 v0, v1;
            v0.x = rndtf(O[mt][nt][0] * inv0); v0.y = rndtf(O[mt][nt][1] * inv0);
            v1.x = rndtf(O[mt][nt][2] * inv1); v1.y = rndtf(O[mt][nt][3] * inv1);
            *(float2*)(obase + (size_t)r * 1024 + c)       = v0;
            *(float2*)(obase + (size_t)(r + 8) * 1024 + c) = v1;
        }
    }
}

// ---------------------------------------------------------------------------
// Launcher
// ---------------------------------------------------------------------------
extern "C" void kernel_launch(void* const* d_in, const int* in_sizes, int n_in,
                              void* d_out, int out_size)
{
    const float* x     = (const float*)d_in[0];
    // d_in[1] = mask: deterministic causal tril -> handled analytically
    const float* Wqkv  = (const float*)d_in[2];
    const float* Wproj = (const float*)d_in[3];
    const float* bproj = (const float*)d_in[4];
    const float* Aqkv  = (const float*)d_in[5];
    const float* Bqkv  = (const float*)d_in[6];
    const float* Aproj = (const float*)d_in[7];
    const float* Bproj = (const float*)d_in[8];

    float *gx, *wq, *wp, *qkv, *att;
    cudaGetSymbolAddress((void**)&gx,  g_x);
    cudaGetSymbolAddress((void**)&wq,  g_Wqkv);
    cudaGetSymbolAddress((void**)&wp,  g_Wproj);
    cudaGetSymbolAddress((void**)&qkv, g_qkv);
    cudaGetSymbolAddress((void**)&att, g_att);

    cudaFuncSetAttribute(gemm_mma<false, true>,
                         cudaFuncAttributeMaxDynamicSharedMemorySize, GEMM_SMEM_BYTES);
    cudaFuncSetAttribute(gemm_mma<true, false>,
                         cudaFuncAttributeMaxDynamicSharedMemorySize, GEMM_SMEM_BYTES);
    cudaFuncSetAttribute(attn_mma,
                         cudaFuncAttributeMaxDynamicSharedMemorySize, ATTN2_SMEM_BYTES);

    // 0) round x to tf32 once
    const int n4 = M_TOK * E_DIM / 4;
    round_tf32<<<(n4 + 255) / 256, 256>>>((const float4*)x, (float4*)gx, n4);

    // 1) fold LoRA into dense weights (tf32-rounded)
    fuse_w<<<(N_QKV * E_DIM + 255) / 256, 256>>>(Wqkv, Aqkv, Bqkv, wq, N_QKV);
    fuse_w<<<(E_DIM * E_DIM + 255) / 256, 256>>>(Wproj, Aproj, Bproj, wp, E_DIM);

    // 2) qkv = x @ Wqkv_eff^T   (tf32 TC; output rounded for attention)
    gemm_mma<false, true><<<dim3(N_QKV / 256, M_TOK / 128), 256, GEMM_SMEM_BYTES>>>(
        gx, wq, nullptr, qkv, E_DIM, N_QKV);

    // 3) causal flash attention (tf32 TC; output rounded for proj GEMM)
    attn_mma<<<dim3(S_LEN / 128, B_NUM * H_NUM), 128, ATTN2_SMEM_BYTES>>>(qkv, att);

    // 4) out = att @ Wproj_eff^T + bproj   (tf32 TC, full fp32 output)
    gemm_mma<true, false><<<dim3(E_DIM / 256, M_TOK / 128), 256, GEMM_SMEM_BYTES>>>(
        att, wp, bproj, (float*)d_out, E_DIM, E_DIM);
}

// round 12
// speedup vs baseline: 1.4267x; 1.4267x over previous
#include <cuda_runtime.h>
#include <cuda_fp16.h>
#include <cstdint>

// Problem constants
#define E_DIM   1024
#define H_NUM   16
#define B_NUM   4
#define S_LEN   2048
#define R_RANK  8
#define M_TOK   (B_NUM * S_LEN)      // 8192
#define N_QKV   (3 * E_DIM)          // 3072
#define LORA_SCALING 2.0f
#define ATTN_SCALE   0.125f          // D^-0.5

// ---------------------------------------------------------------------------
// Scratch (device globals: allocation-free per harness rules)
// ---------------------------------------------------------------------------
__device__ __half g_x[(size_t)M_TOK * E_DIM];     // fp16 x            (16 MB)
__device__ __half g_Wqkv[N_QKV * E_DIM];          // fused QKV weight  (6 MB)
__device__ __half g_Wproj[E_DIM * E_DIM];         // fused proj weight (2 MB)
__device__ __half g_qkv[(size_t)M_TOK * N_QKV];   // qkv activations  (48 MB)
__device__ __half g_att[(size_t)M_TOK * E_DIM];   // attention out    (16 MB)

// ---------------------------------------------------------------------------
// helpers
// ---------------------------------------------------------------------------
__device__ __forceinline__ void mma_f16(float& c0, float& c1, float& c2, float& c3,
                                        uint32_t a0, uint32_t a1, uint32_t a2, uint32_t a3,
                                        uint32_t b0, uint32_t b1) {
    asm volatile(
        "mma.sync.aligned.m16n8k16.row.col.f32.f16.f16.f32 "
        "{%0,%1,%2,%3}, {%4,%5,%6,%7}, {%8,%9}, {%0,%1,%2,%3};"
        : "+f"(c0), "+f"(c1), "+f"(c2), "+f"(c3)
        : "r"(a0), "r"(a1), "r"(a2), "r"(a3), "r"(b0), "r"(b1));
}
__device__ __forceinline__ void ldsm_x4(uint32_t& r0, uint32_t& r1,
                                        uint32_t& r2, uint32_t& r3, uint32_t addr) {
    asm volatile("ldmatrix.sync.aligned.m8n8.x4.shared.b16 {%0,%1,%2,%3}, [%4];"
                 : "=r"(r0), "=r"(r1), "=r"(r2), "=r"(r3) : "r"(addr));
}
__device__ __forceinline__ void ldsm_x4_t(uint32_t& r0, uint32_t& r1,
                                          uint32_t& r2, uint32_t& r3, uint32_t addr) {
    asm volatile("ldmatrix.sync.aligned.m8n8.x4.trans.shared.b16 {%0,%1,%2,%3}, [%4];"
                 : "=r"(r0), "=r"(r1), "=r"(r2), "=r"(r3) : "r"(addr));
}
__device__ __forceinline__ uint32_t pack_h2(float a, float b) {
    __half2 h = __floats2half2_rn(a, b);
    return *(uint32_t*)&h;
}

// ---------------------------------------------------------------------------
// Kernel 0: convert x to fp16 once
// ---------------------------------------------------------------------------
__global__ void to_half(const float4* __restrict__ in, uint2* __restrict__ out, int n4)
{
    int i = blockIdx.x * 256 + threadIdx.x;
    if (i >= n4) return;
    float4 v = in[i];
    uint2 o;
    o.x = pack_h2(v.x, v.y);
    o.y = pack_h2(v.z, v.w);
    out[i] = o;
}

// ---------------------------------------------------------------------------
// Kernel 1: fold LoRA into dense weight:  out = h(W + 2 * (Bm @ Am))
// ---------------------------------------------------------------------------
__global__ void fuse_w(const float* __restrict__ W, const float* __restrict__ Am,
                       const float* __restrict__ Bm, __half* __restrict__ out,
                       int Nrows)
{
    int idx = blockIdx.x * 256 + threadIdx.x;
    if (idx >= Nrows * 1024) return;
    int n = idx >> 10;
    int k = idx & 1023;
    float acc = W[idx];
#pragma unroll
    for (int r = 0; r < R_RANK; r++)
        acc = fmaf(LORA_SCALING * Bm[n * R_RANK + r], Am[r * 1024 + k], acc);
    out[idx] = __float2half_rn(acc);
}

// ---------------------------------------------------------------------------
// fp16 tensor-core GEMM:  C[M,N] = A[M,K] @ W[N,K]^T (+ bias)
//   block 128x128, BK=16, 256 threads (8 warps 2x4, 64x32 per warp)
//   m16n8k16; smem stride 24 halves (48B, ldsm conflict-free)
//   HOUT: write half output; else float (+bias)
// ---------------------------------------------------------------------------
#define GSTR 24

template <bool BIAS, bool HOUT>
__global__ __launch_bounds__(256)
void gemm_h(const __half* __restrict__ A, const __half* __restrict__ W,
            const float* __restrict__ bias, void* __restrict__ Cv,
            int Kn, int Nn)
{
    __shared__ __half Asm[2][128 * GSTR];   // 12 KB
    __shared__ __half Wsm[2][128 * GSTR];   // 12 KB

    const int t    = threadIdx.x;
    const int wid  = t >> 5;
    const int lid  = t & 31;
    const int gid  = lid >> 2;
    const int tg   = lid & 3;
    const int wm   = (wid >> 2) * 64;
    const int wn   = (wid & 3) * 32;
    const int row0 = blockIdx.y << 7;
    const int col0 = blockIdx.x << 7;

    const int mh = lid >> 3;
    const int rr = lid & 7;
    const uint32_t Asm_sh = (uint32_t)__cvta_generic_to_shared(&Asm[0][0]);
    const uint32_t Wsm_sh = (uint32_t)__cvta_generic_to_shared(&Wsm[0][0]);
    const uint32_t a_lane = ((mh & 1) * 8 + rr) * (GSTR * 2) + (mh >> 1) * 16;
    const uint32_t b_lane = ((mh >> 1) * 8 + rr) * (GSTR * 2) + (mh & 1) * 16;

    // loader: 1 thread per row (t<128: A row t ; t>=128: W row t-128), 32B/row
    const bool isW = (t >= 128);
    const int  lrow = t & 127;
    const __half* src = (isW ? W + (size_t)(col0 + lrow) * Kn
                             : A + (size_t)(row0 + lrow) * Kn);

    float acc[4][4][4];
#pragma unroll
    for (int i = 0; i < 4; i++)
#pragma unroll
        for (int j = 0; j < 4; j++)
#pragma unroll
            for (int r = 0; r < 4; r++) acc[i][j][r] = 0.0f;

    const int nkt = Kn >> 4;

    // preload stage 0
    {
        uint4 u0 = *(const uint4*)(src);
        uint4 u1 = *(const uint4*)(src + 8);
        __half* dst = (isW ? &Wsm[0][lrow * GSTR] : &Asm[0][lrow * GSTR]);
        *(uint4*)(dst)     = u0;
        *(uint4*)(dst + 8) = u1;
    }
    __syncthreads();

    for (int kt = 0; kt < nkt; kt++) {
        const int cur = kt & 1, nxt = cur ^ 1;

        uint4 p0, p1;
        if (kt + 1 < nkt) {
            const __half* s = src + ((kt + 1) << 4);
            p0 = *(const uint4*)(s);
            p1 = *(const uint4*)(s + 8);
        }

        {
            const uint32_t abase = Asm_sh + cur * (128 * GSTR * 2);
            const uint32_t bbase = Wsm_sh + cur * (128 * GSTR * 2);
            uint32_t af[4][4], bf[4][2];
#pragma unroll
            for (int mt = 0; mt < 4; mt++)
                ldsm_x4(af[mt][0], af[mt][1], af[mt][2], af[mt][3],
                        abase + (wm + mt * 16) * (GSTR * 2) + a_lane);
#pragma unroll
            for (int p = 0; p < 2; p++)
                ldsm_x4(bf[2*p][0], bf[2*p][1], bf[2*p+1][0], bf[2*p+1][1],
                        bbase + (wn + p * 16) * (GSTR * 2) + b_lane);
#pragma unroll
            for (int mt = 0; mt < 4; mt++)
#pragma unroll
                for (int nt = 0; nt < 4; nt++)
                    mma_f16(acc[mt][nt][0], acc[mt][nt][1],
                            acc[mt][nt][2], acc[mt][nt][3],
                            af[mt][0], af[mt][1], af[mt][2], af[mt][3],
                            bf[nt][0], bf[nt][1]);
        }

        if (kt + 1 < nkt) {
            __half* dst = (isW ? &Wsm[nxt][lrow * GSTR] : &Asm[nxt][lrow * GSTR]);
            *(uint4*)(dst)     = p0;
            *(uint4*)(dst + 8) = p1;
        }
        __syncthreads();
    }

#pragma unroll
    for (int mt = 0; mt < 4; mt++) {
        const int r = row0 + wm + mt * 16 + gid;
#pragma unroll
        for (int nt = 0; nt < 4; nt++) {
            const int c = col0 + wn + nt * 8 + tg * 2;
            if (HOUT) {
                __half* Ch = (__half*)Cv;
                *(uint32_t*)(Ch + (size_t)r * Nn + c) =
                    pack_h2(acc[mt][nt][0], acc[mt][nt][1]);
                *(uint32_t*)(Ch + (size_t)(r + 8) * Nn + c) =
                    pack_h2(acc[mt][nt][2], acc[mt][nt][3]);
            } else {
                float* Cf = (float*)Cv;
                float2 v0, v1;
                v0.x = acc[mt][nt][0]; v0.y = acc[mt][nt][1];
                v1.x = acc[mt][nt][2]; v1.y = acc[mt][nt][3];
                if (BIAS) {
                    float b0 = bias[c], b1 = bias[c + 1];
                    v0.x += b0; v0.y += b1;
                    v1.x += b0; v1.y += b1;
                }
                *(float2*)(Cf + (size_t)r * Nn + c)       = v0;
                *(float2*)(Cf + (size_t)(r + 8) * Nn + c) = v1;
            }
        }
    }
}

// ---------------------------------------------------------------------------
// Kernel 3: causal flash attention, fp16 MMA (m16n8k16), fp32 softmax
//   128 threads (4 warps); q-tile 128 rows; warp w owns q-rows [32w,32w+32)
//   Qs[128][72] Ps[128][72] Ks[64][72] Vs[64][72]  (halves; stride 144B)
//   V fragments via ldmatrix.trans on natural [k][d] layout
// ---------------------------------------------------------------------------
#define ASTR 72
#define ATTN_SMEM_BYTES ((128 + 128 + 64 + 64) * ASTR * 2)   // 55296

__global__ __launch_bounds__(128)
void attn_h(const __half* __restrict__ qkv, __half* __restrict__ out)
{
    extern __shared__ __half smh[];
    __half* Qs = smh;                    // [128][ASTR]
    __half* Ps = Qs + 128 * ASTR;        // [128][ASTR]
    __half* Ks = Ps + 128 * ASTR;        // [64][ASTR]
    __half* Vs = Ks + 64 * ASTR;         // [64][ASTR]

    const int t   = threadIdx.x;
    const int w   = t >> 5;
    const int lid = t & 31;
    const int gid = lid >> 2;
    const int tg  = lid & 3;

    const int mh = lid >> 3;
    const int rr = lid & 7;
    const uint32_t Qs_sh = (uint32_t)__cvta_generic_to_shared(Qs);
    const uint32_t Ps_sh = (uint32_t)__cvta_generic_to_shared(Ps);
    const uint32_t Ks_sh = (uint32_t)__cvta_generic_to_shared(Ks);
    const uint32_t Vs_sh = (uint32_t)__cvta_generic_to_shared(Vs);
    const uint32_t a_lane = ((mh & 1) * 8 + rr) * (ASTR * 2) + (mh >> 1) * 16;  // A (Q/P)
    const uint32_t k_lane = ((mh >> 1) * 8 + rr) * (ASTR * 2) + (mh & 1) * 16;  // K B, non-trans
    const uint32_t v_lane = ((mh & 1) * 8 + rr) * (ASTR * 2) + (mh >> 1) * 16;  // V B, trans

    const int qi = (int)gridDim.x - 1 - (int)blockIdx.x;  // long blocks first
    const int bh = blockIdx.y;
    const int b  = bh >> 4;
    const int h  = bh & 15;

    const __half* qbase = qkv + (size_t)b * S_LEN * 3072 + h * 64;
    const __half* kbase = qbase + 1024;
    const __half* vbase = qbase + 2048;

    // load Q tile: 1 thread per row, 128B, scale by 0.125 (exact)
    {
        const __half* qp = qbase + (size_t)(qi * 128 + t) * 3072;
        __half* dst = &Qs[t * ASTR];
        const __half2 sc = __float2half2_rn(ATTN_SCALE);
#pragma unroll
        for (int jj = 0; jj < 8; jj++) {
            uint4 u = *(const uint4*)(qp + jj * 8);
            __half2* hp = (__half2*)&u;
            hp[0] = __hmul2(hp[0], sc); hp[1] = __hmul2(hp[1], sc);
            hp[2] = __hmul2(hp[2], sc); hp[3] = __hmul2(hp[3], sc);
            *(uint4*)(dst + jj * 8) = u;
        }
    }

    const int R0 = w * 32 + gid;
    float O[2][8][4];
    float rmax[2][2], rsum[2][2];
#pragma unroll
    for (int mt = 0; mt < 2; mt++) {
        rmax[mt][0] = -1e30f; rmax[mt][1] = -1e30f;
        rsum[mt][0] = 0.0f;   rsum[mt][1] = 0.0f;
#pragma unroll
        for (int nt = 0; nt < 8; nt++)
#pragma unroll
            for (int r = 0; r < 4; r++) O[mt][nt][r] = 0.0f;
    }

    // K/V loader mapping: t<64 -> K row t ; t>=64 -> V row t-64
    const int kvrow = t & 63;
    const bool isV  = (t >= 64);

    const int jmax = 2 * qi + 1;
    for (int j = 0; j <= jmax; j++) {
        __syncthreads();   // prior reads of Ks/Vs done (covers Q store on j=0)

        {
            const __half* src = (isV ? vbase : kbase) + (size_t)(j * 64 + kvrow) * 3072;
            __half* dst = (isV ? Vs : Ks) + kvrow * ASTR;
#pragma unroll
            for (int jj = 0; jj < 8; jj++)
                *(uint4*)(dst + jj * 8) = *(const uint4*)(src + jj * 8);
        }
        __syncthreads();

        if (j * 64 > qi * 128 + w * 32 + 31) continue;

        // ---- S = Q @ K^T : 4 k-steps of d16 ----
        float sacc[2][8][4];
#pragma unroll
        for (int mt = 0; mt < 2; mt++)
#pragma unroll
            for (int nt = 0; nt < 8; nt++)
#pragma unroll
                for (int r = 0; r < 4; r++) sacc[mt][nt][r] = 0.0f;

#pragma unroll
        for (int kk = 0; kk < 4; kk++) {
            uint32_t a[2][4], bk[8][2];
#pragma unroll
            for (int mt = 0; mt < 2; mt++)
                ldsm_x4(a[mt][0], a[mt][1], a[mt][2], a[mt][3],
                        Qs_sh + (w * 32 + mt * 16) * (ASTR * 2) + kk * 32 + a_lane);
#pragma unroll
            for (int p = 0; p < 4; p++)
                ldsm_x4(bk[2*p][0], bk[2*p][1], bk[2*p+1][0], bk[2*p+1][1],
                        Ks_sh + (p * 16) * (ASTR * 2) + kk * 32 + k_lane);
#pragma unroll
            for (int nt = 0; nt < 8; nt++) {
                mma_f16(sacc[0][nt][0], sacc[0][nt][1], sacc[0][nt][2], sacc[0][nt][3],
                        a[0][0], a[0][1], a[0][2], a[0][3], bk[nt][0], bk[nt][1]);
                mma_f16(sacc[1][nt][0], sacc[1][nt][1], sacc[1][nt][2], sacc[1][nt][3],
                        a[1][0], a[1][1], a[1][2], a[1][3], bk[nt][0], bk[nt][1]);
            }
        }

        // causal mask
        if (j * 64 + 63 > qi * 128 + w * 32) {
#pragma unroll
            for (int mt = 0; mt < 2; mt++) {
                const int rg0 = qi * 128 + R0 + mt * 16;
                const int rg1 = rg0 + 8;
#pragma unroll
                for (int nt = 0; nt < 8; nt++) {
                    const int cg = j * 64 + nt * 8 + 2 * tg;
                    if (cg     > rg0) sacc[mt][nt][0] = -1e30f;
                    if (cg + 1 > rg0) sacc[mt][nt][1] = -1e30f;
                    if (cg     > rg1) sacc[mt][nt][2] = -1e30f;
                    if (cg + 1 > rg1) sacc[mt][nt][3] = -1e30f;
                }
            }
        }

        // ---- online softmax ----
#pragma unroll
        for (int mt = 0; mt < 2; mt++)
#pragma unroll
            for (int hf = 0; hf < 2; hf++) {
                const int i0 = hf * 2, i1 = hf * 2 + 1;
                float m = -1e30f;
#pragma unroll
                for (int nt = 0; nt < 8; nt++)
                    m = fmaxf(m, fmaxf(sacc[mt][nt][i0], sacc[mt][nt][i1]));
                m = fmaxf(m, __shfl_xor_sync(0xffffffffu, m, 1));
                m = fmaxf(m, __shfl_xor_sync(0xffffffffu, m, 2));

                float nm = fmaxf(rmax[mt][hf], m);
                float corr = __expf(rmax[mt][hf] - nm);
                rmax[mt][hf] = nm;

                const int prow = R0 + mt * 16 + hf * 8;
                float ls = 0.0f;
#pragma unroll
                for (int nt = 0; nt < 8; nt++) {
                    float p0 = __expf(sacc[mt][nt][i0] - nm);
                    float p1 = __expf(sacc[mt][nt][i1] - nm);
                    ls += p0 + p1;
                    *(uint32_t*)&Ps[prow * ASTR + nt * 8 + 2 * tg] = pack_h2(p0, p1);
                }
                ls += __shfl_xor_sync(0xffffffffu, ls, 1);
                ls += __shfl_xor_sync(0xffffffffu, ls, 2);
                rsum[mt][hf] = rsum[mt][hf] * corr + ls;

#pragma unroll
                for (int nt = 0; nt < 8; nt++) {
                    O[mt][nt][i0] *= corr;
                    O[mt][nt][i1] *= corr;
                }
            }
        __syncwarp();

        // ---- O += P @ V : 4 k-steps of key16; V frags via ldmatrix.trans ----
#pragma unroll
        for (int kk = 0; kk < 4; kk++) {
            uint32_t a[2][4], bv[8][2];
#pragma unroll
            for (int mt = 0; mt < 2; mt++)
                ldsm_x4(a[mt][0], a[mt][1], a[mt][2], a[mt][3],
                        Ps_sh + (w * 32 + mt * 16) * (ASTR * 2) + kk * 32 + a_lane);
#pragma unroll
            for (int p = 0; p < 4; p++)
                ldsm_x4_t(bv[2*p][0], bv[2*p][1], bv[2*p+1][0], bv[2*p+1][1],
                          Vs_sh + (kk * 16) * (ASTR * 2) + p * 32 + v_lane);
#pragma unroll
            for (int nt = 0; nt < 8; nt++) {
                mma_f16(O[0][nt][0], O[0][nt][1], O[0][nt][2], O[0][nt][3],
                        a[0][0], a[0][1], a[0][2], a[0][3], bv[nt][0], bv[nt][1]);
                mma_f16(O[1][nt][0], O[1][nt][1], O[1][nt][2], O[1][nt][3],
                        a[1][0], a[1][1], a[1][2], a[1][3], bv[nt][0], bv[nt][1]);
            }
        }
    }

    // epilogue: normalize + store half
    __half* obase = out + ((size_t)b * S_LEN + qi * 128) * 1024 + h * 64;
#pragma unroll
    for (int mt = 0; mt < 2; mt++) {
        const float inv0 = 1.0f / rsum[mt][0];
        const float inv1 = 1.0f / rsum[mt][1];
        const int r = R0 + mt * 16;
#pragma unroll
        for (int nt = 0; nt < 8; nt++) {
            const int c = nt * 8 + 2 * tg;
            *(uint32_t*)(obase + (size_t)r * 1024 + c) =
                pack_h2(O[mt][nt][0] * inv0, O[mt][nt][1] * inv0);
            *(uint32_t*)(obase + (size_t)(r + 8) * 1024 + c) =
                pack_h2(O[mt][nt][2] * inv1, O[mt][nt][3] * inv1);
        }
    }
}

// ---------------------------------------------------------------------------
// Launcher
// ---------------------------------------------------------------------------
extern "C" void kernel_launch(void* const* d_in, const int* in_sizes, int n_in,
                              void* d_out, int out_size)
{
    const float* x     = (const float*)d_in[0];
    // d_in[1] = mask: deterministic causal tril -> handled analytically
    const float* Wqkv  = (const float*)d_in[2];
    const float* Wproj = (const float*)d_in[3];
    const float* bproj = (const float*)d_in[4];
    const float* Aqkv  = (const float*)d_in[5];
    const float* Bqkv  = (const float*)d_in[6];
    const float* Aproj = (const float*)d_in[7];
    const float* Bproj = (const float*)d_in[8];

    __half *gx, *wq, *wp, *qkv, *att;
    cudaGetSymbolAddress((void**)&gx,  g_x);
    cudaGetSymbolAddress((void**)&wq,  g_Wqkv);
    cudaGetSymbolAddress((void**)&wp,  g_Wproj);
    cudaGetSymbolAddress((void**)&qkv, g_qkv);
    cudaGetSymbolAddress((void**)&att, g_att);

    cudaFuncSetAttribute(attn_h,
                         cudaFuncAttributeMaxDynamicSharedMemorySize, ATTN_SMEM_BYTES);

    // 0) x -> fp16
    const int n4 = M_TOK * E_DIM / 4;
    to_half<<<(n4 + 255) / 256, 256>>>((const float4*)x, (uint2*)gx, n4);

    // 1) fold LoRA into dense weights (fp16)
    fuse_w<<<(N_QKV * E_DIM + 255) / 256, 256>>>(Wqkv, Aqkv, Bqkv, wq, N_QKV);
    fuse_w<<<(E_DIM * E_DIM + 255) / 256, 256>>>(Wproj, Aproj, Bproj, wp, E_DIM);

    // 2) qkv = x @ Wqkv_eff^T   (fp16 TC, half output)
    gemm_h<false, true><<<dim3(N_QKV / 128, M_TOK / 128), 256>>>(
        gx, wq, nullptr, qkv, E_DIM, N_QKV);

    // 3) causal flash attention (fp16 TC, half output)
    attn_h<<<dim3(S_LEN / 128, B_NUM * H_NUM), 128, ATTN_SMEM_BYTES>>>(qkv, att);

    // 4) out = att @ Wproj_eff^T + bproj   (fp16 TC, f32 output)
    gemm_h<true, false><<<dim3(E_DIM / 128, M_TOK / 128), 256>>>(
        att, wp, bproj, d_out, E_DIM, E_DIM);
}

// round 13
// speedup vs baseline: 1.4433x; 1.0116x over previous
#include <cuda_runtime.h>
#include <cuda_fp16.h>
#include <cstdint>

// Problem constants
#define E_DIM   1024
#define H_NUM   16
#define B_NUM   4
#define S_LEN   2048
#define R_RANK  8
#define M_TOK   (B_NUM * S_LEN)      // 8192
#define N_QKV   (3 * E_DIM)          // 3072
#define LORA_SCALING 2.0f
#define ATTN_SCALE   0.125f          // D^-0.5

// ---------------------------------------------------------------------------
// Scratch (device globals: allocation-free per harness rules)
// ---------------------------------------------------------------------------
__device__ __half g_x[(size_t)M_TOK * E_DIM];     // fp16 x            (16 MB)
__device__ __half g_Wqkv[N_QKV * E_DIM];          // fused QKV weight  (6 MB)
__device__ __half g_Wproj[E_DIM * E_DIM];         // fused proj weight (2 MB)
__device__ __half g_qkv[(size_t)M_TOK * N_QKV];   // qkv activations  (48 MB)
__device__ __half g_att[(size_t)M_TOK * E_DIM];   // attention out    (16 MB)

// ---------------------------------------------------------------------------
// helpers
// ---------------------------------------------------------------------------
__device__ __forceinline__ void mma_f16(float& c0, float& c1, float& c2, float& c3,
                                        uint32_t a0, uint32_t a1, uint32_t a2, uint32_t a3,
                                        uint32_t b0, uint32_t b1) {
    asm volatile(
        "mma.sync.aligned.m16n8k16.row.col.f32.f16.f16.f32 "
        "{%0,%1,%2,%3}, {%4,%5,%6,%7}, {%8,%9}, {%0,%1,%2,%3};"
        : "+f"(c0), "+f"(c1), "+f"(c2), "+f"(c3)
        : "r"(a0), "r"(a1), "r"(a2), "r"(a3), "r"(b0), "r"(b1));
}
__device__ __forceinline__ void ldsm_x4(uint32_t& r0, uint32_t& r1,
                                        uint32_t& r2, uint32_t& r3, uint32_t addr) {
    asm volatile("ldmatrix.sync.aligned.m8n8.x4.shared.b16 {%0,%1,%2,%3}, [%4];"
                 : "=r"(r0), "=r"(r1), "=r"(r2), "=r"(r3) : "r"(addr));
}
__device__ __forceinline__ void ldsm_x4_t(uint32_t& r0, uint32_t& r1,
                                          uint32_t& r2, uint32_t& r3, uint32_t addr) {
    asm volatile("ldmatrix.sync.aligned.m8n8.x4.trans.shared.b16 {%0,%1,%2,%3}, [%4];"
                 : "=r"(r0), "=r"(r1), "=r"(r2), "=r"(r3) : "r"(addr));
}
__device__ __forceinline__ uint32_t pack_h2(float a, float b) {
    __half2 h = __floats2half2_rn(a, b);
    return *(uint32_t*)&h;
}

// ---------------------------------------------------------------------------
// Kernel 0: convert x to fp16 once
// ---------------------------------------------------------------------------
__global__ void to_half(const float4* __restrict__ in, uint2* __restrict__ out, int n4)
{
    int i = blockIdx.x * 256 + threadIdx.x;
    if (i >= n4) return;
    float4 v = in[i];
    uint2 o;
    o.x = pack_h2(v.x, v.y);
    o.y = pack_h2(v.z, v.w);
    out[i] = o;
}

// ---------------------------------------------------------------------------
// Kernel 1: fold LoRA into dense weight:  out = h(W + 2 * (Bm @ Am))
// ---------------------------------------------------------------------------
__global__ void fuse_w(const float* __restrict__ W, const float* __restrict__ Am,
                       const float* __restrict__ Bm, __half* __restrict__ out,
                       int Nrows)
{
    int idx = blockIdx.x * 256 + threadIdx.x;
    if (idx >= Nrows * 1024) return;
    int n = idx >> 10;
    int k = idx & 1023;
    float acc = W[idx];
#pragma unroll
    for (int r = 0; r < R_RANK; r++)
        acc = fmaf(LORA_SCALING * Bm[n * R_RANK + r], Am[r * 1024 + k], acc);
    out[idx] = __float2half_rn(acc);
}

// ---------------------------------------------------------------------------
// fp16 tensor-core GEMM:  C[M,N] = A[M,K] @ W[N,K]^T (+ bias)
//   block 128x128, BK=16, 128 threads (4 warps 2x2, 64x64 per warp)
//   m16n8k16; smem stride 24 halves; 2 CTA/SM; register prefetch
// ---------------------------------------------------------------------------
#define GSTR 24

template <bool BIAS, bool HOUT>
__global__ __launch_bounds__(128)
void gemm_h(const __half* __restrict__ A, const __half* __restrict__ W,
            const float* __restrict__ bias, void* __restrict__ Cv,
            int Kn, int Nn)
{
    __shared__ __half Asm[2][128 * GSTR];   // 6 KB each stage
    __shared__ __half Wsm[2][128 * GSTR];

    const int t    = threadIdx.x;
    const int wid  = t >> 5;
    const int lid  = t & 31;
    const int gid  = lid >> 2;
    const int tg   = lid & 3;
    const int wm   = (wid >> 1) * 64;     // 0 or 64
    const int wn   = (wid & 1) * 64;      // 0 or 64
    const int row0 = blockIdx.y << 7;
    const int col0 = blockIdx.x << 7;

    const int mh = lid >> 3;
    const int rr = lid & 7;
    const uint32_t Asm_sh = (uint32_t)__cvta_generic_to_shared(&Asm[0][0]);
    const uint32_t Wsm_sh = (uint32_t)__cvta_generic_to_shared(&Wsm[0][0]);
    const uint32_t a_lane = ((mh & 1) * 8 + rr) * (GSTR * 2) + (mh >> 1) * 16;
    const uint32_t b_lane = ((mh >> 1) * 8 + rr) * (GSTR * 2) + (mh & 1) * 16;

    // loader: each thread owns A row t and W row t (32B per row per kt)
    const __half* Ap = A + (size_t)(row0 + t) * Kn;
    const __half* Wp = W + (size_t)(col0 + t) * Kn;

    float acc[4][8][4];
#pragma unroll
    for (int i = 0; i < 4; i++)
#pragma unroll
        for (int j = 0; j < 8; j++)
#pragma unroll
            for (int r = 0; r < 4; r++) acc[i][j][r] = 0.0f;

    const int nkt = Kn >> 4;

    // preload stage 0
    {
        uint4 a0 = *(const uint4*)(Ap);
        uint4 a1 = *(const uint4*)(Ap + 8);
        uint4 w0 = *(const uint4*)(Wp);
        uint4 w1 = *(const uint4*)(Wp + 8);
        *(uint4*)&Asm[0][t * GSTR]     = a0;
        *(uint4*)&Asm[0][t * GSTR + 8] = a1;
        *(uint4*)&Wsm[0][t * GSTR]     = w0;
        *(uint4*)&Wsm[0][t * GSTR + 8] = w1;
    }
    __syncthreads();

    for (int kt = 0; kt < nkt; kt++) {
        const int cur = kt & 1, nxt = cur ^ 1;

        uint4 pa0, pa1, pw0, pw1;
        if (kt + 1 < nkt) {
            const int k0 = (kt + 1) << 4;
            pa0 = *(const uint4*)(Ap + k0);
            pa1 = *(const uint4*)(Ap + k0 + 8);
            pw0 = *(const uint4*)(Wp + k0);
            pw1 = *(const uint4*)(Wp + k0 + 8);
        }

        {
            const uint32_t abase = Asm_sh + cur * (128 * GSTR * 2);
            const uint32_t bbase = Wsm_sh + cur * (128 * GSTR * 2);
            uint32_t af[4][4], bf[8][2];
#pragma unroll
            for (int mt = 0; mt < 4; mt++)
                ldsm_x4(af[mt][0], af[mt][1], af[mt][2], af[mt][3],
                        abase + (wm + mt * 16) * (GSTR * 2) + a_lane);
#pragma unroll
            for (int p = 0; p < 4; p++)
                ldsm_x4(bf[2*p][0], bf[2*p][1], bf[2*p+1][0], bf[2*p+1][1],
                        bbase + (wn + p * 16) * (GSTR * 2) + b_lane);
#pragma unroll
            for (int mt = 0; mt < 4; mt++)
#pragma unroll
                for (int nt = 0; nt < 8; nt++)
                    mma_f16(acc[mt][nt][0], acc[mt][nt][1],
                            acc[mt][nt][2], acc[mt][nt][3],
                            af[mt][0], af[mt][1], af[mt][2], af[mt][3],
                            bf[nt][0], bf[nt][1]);
        }

        if (kt + 1 < nkt) {
            *(uint4*)&Asm[nxt][t * GSTR]     = pa0;
            *(uint4*)&Asm[nxt][t * GSTR + 8] = pa1;
            *(uint4*)&Wsm[nxt][t * GSTR]     = pw0;
            *(uint4*)&Wsm[nxt][t * GSTR + 8] = pw1;
        }
        __syncthreads();
    }

#pragma unroll
    for (int mt = 0; mt < 4; mt++) {
        const int r = row0 + wm + mt * 16 + gid;
#pragma unroll
        for (int nt = 0; nt < 8; nt++) {
            const int c = col0 + wn + nt * 8 + tg * 2;
            if (HOUT) {
                __half* Ch = (__half*)Cv;
                *(uint32_t*)(Ch + (size_t)r * Nn + c) =
                    pack_h2(acc[mt][nt][0], acc[mt][nt][1]);
                *(uint32_t*)(Ch + (size_t)(r + 8) * Nn + c) =
                    pack_h2(acc[mt][nt][2], acc[mt][nt][3]);
            } else {
                float* Cf = (float*)Cv;
                float2 v0, v1;
                v0.x = acc[mt][nt][0]; v0.y = acc[mt][nt][1];
                v1.x = acc[mt][nt][2]; v1.y = acc[mt][nt][3];
                if (BIAS) {
                    float b0 = bias[c], b1 = bias[c + 1];
                    v0.x += b0; v0.y += b1;
                    v1.x += b0; v1.y += b1;
                }
                *(float2*)(Cf + (size_t)r * Nn + c)       = v0;
                *(float2*)(Cf + (size_t)(r + 8) * Nn + c) = v1;
            }
        }
    }
}

// ---------------------------------------------------------------------------
// Kernel 3: causal flash attention, fp16 MMA (m16n8k16), fp32 softmax
//   (unchanged from round 12)
// ---------------------------------------------------------------------------
#define ASTR 72
#define ATTN_SMEM_BYTES ((128 + 128 + 64 + 64) * ASTR * 2)   // 55296

__global__ __launch_bounds__(128)
void attn_h(const __half* __restrict__ qkv, __half* __restrict__ out)
{
    extern __shared__ __half smh[];
    __half* Qs = smh;                    // [128][ASTR]
    __half* Ps = Qs + 128 * ASTR;        // [128][ASTR]
    __half* Ks = Ps + 128 * ASTR;        // [64][ASTR]
    __half* Vs = Ks + 64 * ASTR;         // [64][ASTR]

    const int t   = threadIdx.x;
    const int w   = t >> 5;
    const int lid = t & 31;
    const int gid = lid >> 2;
    const int tg  = lid & 3;

    const int mh = lid >> 3;
    const int rr = lid & 7;
    const uint32_t Qs_sh = (uint32_t)__cvta_generic_to_shared(Qs);
    const uint32_t Ps_sh = (uint32_t)__cvta_generic_to_shared(Ps);
    const uint32_t Ks_sh = (uint32_t)__cvta_generic_to_shared(Ks);
    const uint32_t Vs_sh = (uint32_t)__cvta_generic_to_shared(Vs);
    const uint32_t a_lane = ((mh & 1) * 8 + rr) * (ASTR * 2) + (mh >> 1) * 16;  // A (Q/P)
    const uint32_t k_lane = ((mh >> 1) * 8 + rr) * (ASTR * 2) + (mh & 1) * 16;  // K B, non-trans
    const uint32_t v_lane = ((mh & 1) * 8 + rr) * (ASTR * 2) + (mh >> 1) * 16;  // V B, trans

    const int qi = (int)gridDim.x - 1 - (int)blockIdx.x;  // long blocks first
    const int bh = blockIdx.y;
    const int b  = bh >> 4;
    const int h  = bh & 15;

    const __half* qbase = qkv + (size_t)b * S_LEN * 3072 + h * 64;
    const __half* kbase = qbase + 1024;
    const __half* vbase = qbase + 2048;

    // load Q tile: 1 thread per row, 128B, scale by 0.125 (exact)
    {
        const __half* qp = qbase + (size_t)(qi * 128 + t) * 3072;
        __half* dst = &Qs[t * ASTR];
        const __half2 sc = __float2half2_rn(ATTN_SCALE);
#pragma unroll
        for (int jj = 0; jj < 8; jj++) {
            uint4 u = *(const uint4*)(qp + jj * 8);
            __half2* hp = (__half2*)&u;
            hp[0] = __hmul2(hp[0], sc); hp[1] = __hmul2(hp[1], sc);
            hp[2] = __hmul2(hp[2], sc); hp[3] = __hmul2(hp[3], sc);
            *(uint4*)(dst + jj * 8) = u;
        }
    }

    const int R0 = w * 32 + gid;
    float O[2][8][4];
    float rmax[2][2], rsum[2][2];
#pragma unroll
    for (int mt = 0; mt < 2; mt++) {
        rmax[mt][0] = -1e30f; rmax[mt][1] = -1e30f;
        rsum[mt][0] = 0.0f;   rsum[mt][1] = 0.0f;
#pragma unroll
        for (int nt = 0; nt < 8; nt++)
#pragma unroll
            for (int r = 0; r < 4; r++) O[mt][nt][r] = 0.0f;
    }

    // K/V loader mapping: t<64 -> K row t ; t>=64 -> V row t-64
    const int kvrow = t & 63;
    const bool isV  = (t >= 64);

    const int jmax = 2 * qi + 1;
    for (int j = 0; j <= jmax; j++) {
        __syncthreads();   // prior reads of Ks/Vs done (covers Q store on j=0)

        {
            const __half* src = (isV ? vbase : kbase) + (size_t)(j * 64 + kvrow) * 3072;
            __half* dst = (isV ? Vs : Ks) + kvrow * ASTR;
#pragma unroll
            for (int jj = 0; jj < 8; jj++)
                *(uint4*)(dst + jj * 8) = *(const uint4*)(src + jj * 8);
        }
        __syncthreads();

        if (j * 64 > qi * 128 + w * 32 + 31) continue;

        // ---- S = Q @ K^T : 4 k-steps of d16 ----
        float sacc[2][8][4];
#pragma unroll
        for (int mt = 0; mt < 2; mt++)
#pragma unroll
            for (int nt = 0; nt < 8; nt++)
#pragma unroll
                for (int r = 0; r < 4; r++) sacc[mt][nt][r] = 0.0f;

#pragma unroll
        for (int kk = 0; kk < 4; kk++) {
            uint32_t a[2][4], bk[8][2];
#pragma unroll
            for (int mt = 0; mt < 2; mt++)
                ldsm_x4(a[mt][0], a[mt][1], a[mt][2], a[mt][3],
                        Qs_sh + (w * 32 + mt * 16) * (ASTR * 2) + kk * 32 + a_lane);
#pragma unroll
            for (int p = 0; p < 4; p++)
                ldsm_x4(bk[2*p][0], bk[2*p][1], bk[2*p+1][0], bk[2*p+1][1],
                        Ks_sh + (p * 16) * (ASTR * 2) + kk * 32 + k_lane);
#pragma unroll
            for (int nt = 0; nt < 8; nt++) {
                mma_f16(sacc[0][nt][0], sacc[0][nt][1], sacc[0][nt][2], sacc[0][nt][3],
                        a[0][0], a[0][1], a[0][2], a[0][3], bk[nt][0], bk[nt][1]);
                mma_f16(sacc[1][nt][0], sacc[1][nt][1], sacc[1][nt][2], sacc[1][nt][3],
                        a[1][0], a[1][1], a[1][2], a[1][3], bk[nt][0], bk[nt][1]);
            }
        }

        // causal mask
        if (j * 64 + 63 > qi * 128 + w * 32) {
#pragma unroll
            for (int mt = 0; mt < 2; mt++) {
                const int rg0 = qi * 128 + R0 + mt * 16;
                const int rg1 = rg0 + 8;
#pragma unroll
                for (int nt = 0; nt < 8; nt++) {
                    const int cg = j * 64 + nt * 8 + 2 * tg;
                    if (cg     > rg0) sacc[mt][nt][0] = -1e30f;
                    if (cg + 1 > rg0) sacc[mt][nt][1] = -1e30f;
                    if (cg     > rg1) sacc[mt][nt][2] = -1e30f;
                    if (cg + 1 > rg1) sacc[mt][nt][3] = -1e30f;
                }
            }
        }

        // ---- online softmax ----
#pragma unroll
        for (int mt = 0; mt < 2; mt++)
#pragma unroll
            for (int hf = 0; hf < 2; hf++) {
                const int i0 = hf * 2, i1 = hf * 2 + 1;
                float m = -1e30f;
#pragma unroll
                for (int nt = 0; nt < 8; nt++)
                    m = fmaxf(m, fmaxf(sacc[mt][nt][i0], sacc[mt][nt][i1]));
                m = fmaxf(m, __shfl_xor_sync(0xffffffffu, m, 1));
                m = fmaxf(m, __shfl_xor_sync(0xffffffffu, m, 2));

                float nm = fmaxf(rmax[mt][hf], m);
                float corr = __expf(rmax[mt][hf] - nm);
                rmax[mt][hf] = nm;

                const int prow = R0 + mt * 16 + hf * 8;
                float ls = 0.0f;
#pragma unroll
                for (int nt = 0; nt < 8; nt++) {
                    float p0 = __expf(sacc[mt][nt][i0] - nm);
                    float p1 = __expf(sacc[mt][nt][i1] - nm);
                    ls += p0 + p1;
                    *(uint32_t*)&Ps[prow * ASTR + nt * 8 + 2 * tg] = pack_h2(p0, p1);
                }
                ls += __shfl_xor_sync(0xffffffffu, ls, 1);
                ls += __shfl_xor_sync(0xffffffffu, ls, 2);
                rsum[mt][hf] = rsum[mt][hf] * corr + ls;

#pragma unroll
                for (int nt = 0; nt < 8; nt++) {
                    O[mt][nt][i0] *= corr;
                    O[mt][nt][i1] *= corr;
                }
            }
        __syncwarp();

        // ---- O += P @ V : 4 k-steps of key16; V frags via ldmatrix.trans ----
#pragma unroll
        for (int kk = 0; kk < 4; kk++) {
            uint32_t a[2][4], bv[8][2];
#pragma unroll
            for (int mt = 0; mt < 2; mt++)
                ldsm_x4(a[mt][0], a[mt][1], a[mt][2], a[mt][3],
                        Ps_sh + (w * 32 + mt * 16) * (ASTR * 2) + kk * 32 + a_lane);
#pragma unroll
            for (int p = 0; p < 4; p++)
                ldsm_x4_t(bv[2*p][0], bv[2*p][1], bv[2*p+1][0], bv[2*p+1][1],
                          Vs_sh + (kk * 16) * (ASTR * 2) + p * 32 + v_lane);
#pragma unroll
            for (int nt = 0; nt < 8; nt++) {
                mma_f16(O[0][nt][0], O[0][nt][1], O[0][nt][2], O[0][nt][3],
                        a[0][0], a[0][1], a[0][2], a[0][3], bv[nt][0], bv[nt][1]);
                mma_f16(O[1][nt][0], O[1][nt][1], O[1][nt][2], O[1][nt][3],
                        a[1][0], a[1][1], a[1][2], a[1][3], bv[nt][0], bv[nt][1]);
            }
        }
    }

    // epilogue: normalize + store half
    __half* obase = out + ((size_t)b * S_LEN + qi * 128) * 1024 + h * 64;
#pragma unroll
    for (int mt = 0; mt < 2; mt++) {
        const float inv0 = 1.0f / rsum[mt][0];
        const float inv1 = 1.0f / rsum[mt][1];
        const int r = R0 + mt * 16;
#pragma unroll
        for (int nt = 0; nt < 8; nt++) {
            const int c = nt * 8 + 2 * tg;
            *(uint32_t*)(obase + (size_t)r * 1024 + c) =
                pack_h2(O[mt][nt][0] * inv0, O[mt][nt][1] * inv0);
            *(uint32_t*)(obase + (size_t)(r + 8) * 1024 + c) =
                pack_h2(O[mt][nt][2] * inv1, O[mt][nt][3] * inv1);
        }
    }
}

// ---------------------------------------------------------------------------
// Launcher
// ---------------------------------------------------------------------------
extern "C" void kernel_launch(void* const* d_in, const int* in_sizes, int n_in,
                              void* d_out, int out_size)
{
    const float* x     = (const float*)d_in[0];
    // d_in[1] = mask: deterministic causal tril -> handled analytically
    const float* Wqkv  = (const float*)d_in[2];
    const float* Wproj = (const float*)d_in[3];
    const float* bproj = (const float*)d_in[4];
    const float* Aqkv  = (const float*)d_in[5];
    const float* Bqkv  = (const float*)d_in[6];
    const float* Aproj = (const float*)d_in[7];
    const float* Bproj = (const float*)d_in[8];

    __half *gx, *wq, *wp, *qkv, *att;
    cudaGetSymbolAddress((void**)&gx,  g_x);
    cudaGetSymbolAddress((void**)&wq,  g_Wqkv);
    cudaGetSymbolAddress((void**)&wp,  g_Wproj);
    cudaGetSymbolAddress((void**)&qkv, g_qkv);
    cudaGetSymbolAddress((void**)&att, g_att);

    cudaFuncSetAttribute(attn_h,
                         cudaFuncAttributeMaxDynamicSharedMemorySize, ATTN_SMEM_BYTES);

    // 0) x -> fp16
    const int n4 = M_TOK * E_DIM / 4;
    to_half<<<(n4 + 255) / 256, 256>>>((const float4*)x, (uint2*)gx, n4);

    // 1) fold LoRA into dense weights (fp16)
    fuse_w<<<(N_QKV * E_DIM + 255) / 256, 256>>>(Wqkv, Aqkv, Bqkv, wq, N_QKV);
    fuse_w<<<(E_DIM * E_DIM + 255) / 256, 256>>>(Wproj, Aproj, Bproj, wp, E_DIM);

    // 2) qkv = x @ Wqkv_eff^T   (fp16 TC, half output; 128-thread CTAs)
    gemm_h<false, true><<<dim3(N_QKV / 128, M_TOK / 128), 128>>>(
        gx, wq, nullptr, qkv, E_DIM, N_QKV);

    // 3) causal flash attention (fp16 TC, half output)
    attn_h<<<dim3(S_LEN / 128, B_NUM * H_NUM), 128, ATTN_SMEM_BYTES>>>(qkv, att);

    // 4) out = att @ Wproj_eff^T + bproj   (fp16 TC, f32 output)
    gemm_h<true, false><<<dim3(E_DIM / 128, M_TOK / 128), 128>>>(
        att, wp, bproj, d_out, E_DIM, E_DIM);
}

// round 15
// speedup vs baseline: 1.6282x; 1.1281x over previous
#include <cuda_runtime.h>
#include <cuda_fp16.h>
#include <cstdint>

// Problem constants
#define E_DIM   1024
#define H_NUM   16
#define B_NUM   4
#define S_LEN   2048
#define R_RANK  8
#define M_TOK   (B_NUM * S_LEN)      // 8192
#define N_QKV   (3 * E_DIM)          // 3072
#define LORA_SCALING 2.0f
#define ATTN_SCALE   0.125f          // D^-0.5

// ---------------------------------------------------------------------------
// Scratch (device globals: allocation-free per harness rules)
// ---------------------------------------------------------------------------
__device__ __half g_x[(size_t)M_TOK * E_DIM];     // fp16 x            (16 MB)
__device__ __half g_Wqkv[N_QKV * E_DIM];          // fused QKV weight  (6 MB)
__device__ __half g_Wproj[E_DIM * E_DIM];         // fused proj weight (2 MB)
__device__ __half g_qkv[(size_t)M_TOK * N_QKV];   // qkv activations  (48 MB)
__device__ __half g_att[(size_t)M_TOK * E_DIM];   // attention out    (16 MB)

// ---------------------------------------------------------------------------
// helpers
// ---------------------------------------------------------------------------
__device__ __forceinline__ void mma_f16(float& c0, float& c1, float& c2, float& c3,
                                        uint32_t a0, uint32_t a1, uint32_t a2, uint32_t a3,
                                        uint32_t b0, uint32_t b1) {
    asm volatile(
        "mma.sync.aligned.m16n8k16.row.col.f32.f16.f16.f32 "
        "{%0,%1,%2,%3}, {%4,%5,%6,%7}, {%8,%9}, {%0,%1,%2,%3};"
        : "+f"(c0), "+f"(c1), "+f"(c2), "+f"(c3)
        : "r"(a0), "r"(a1), "r"(a2), "r"(a3), "r"(b0), "r"(b1));
}
__device__ __forceinline__ void ldsm_x4(uint32_t& r0, uint32_t& r1,
                                        uint32_t& r2, uint32_t& r3, uint32_t addr) {
    asm volatile("ldmatrix.sync.aligned.m8n8.x4.shared.b16 {%0,%1,%2,%3}, [%4];"
                 : "=r"(r0), "=r"(r1), "=r"(r2), "=r"(r3) : "r"(addr));
}
__device__ __forceinline__ void ldsm_x4_t(uint32_t& r0, uint32_t& r1,
                                          uint32_t& r2, uint32_t& r3, uint32_t addr) {
    asm volatile("ldmatrix.sync.aligned.m8n8.x4.trans.shared.b16 {%0,%1,%2,%3}, [%4];"
                 : "=r"(r0), "=r"(r1), "=r"(r2), "=r"(r3) : "r"(addr));
}
__device__ __forceinline__ uint32_t pack_h2(float a, float b) {
    __half2 h = __floats2half2_rn(a, b);
    return *(uint32_t*)&h;
}
__device__ __forceinline__ void cp16(uint32_t dst, const void* src) {
    asm volatile("cp.async.cg.shared.global [%0], [%1], 16;"
                 :: "r"(dst), "l"(src) : "memory");
}
#define CP_COMMIT() asm volatile("cp.async.commit_group;" ::: "memory")
#define CP_WAIT0()  asm volatile("cp.async.wait_group 0;" ::: "memory")

// ---------------------------------------------------------------------------
// Kernel 0: convert x to fp16 once
// ---------------------------------------------------------------------------
__global__ void to_half(const float4* __restrict__ in, uint2* __restrict__ out, int n4)
{
    int i = blockIdx.x * 256 + threadIdx.x;
    if (i >= n4) return;
    float4 v = in[i];
    uint2 o;
    o.x = pack_h2(v.x, v.y);
    o.y = pack_h2(v.z, v.w);
    out[i] = o;
}

// ---------------------------------------------------------------------------
// Kernel 1: fold LoRA into dense weight:  out = h(W + 2 * (Bm @ Am))
// ---------------------------------------------------------------------------
__global__ void fuse_w(const float* __restrict__ W, const float* __restrict__ Am,
                       const float* __restrict__ Bm, __half* __restrict__ out,
                       int Nrows)
{
    int idx = blockIdx.x * 256 + threadIdx.x;
    if (idx >= Nrows * 1024) return;
    int n = idx >> 10;
    int k = idx & 1023;
    float acc = W[idx];
#pragma unroll
    for (int r = 0; r < R_RANK; r++)
        acc = fmaf(LORA_SCALING * Bm[n * R_RANK + r], Am[r * 1024 + k], acc);
    out[idx] = __float2half_rn(acc);
}

// ---------------------------------------------------------------------------
// fp16 tensor-core GEMM:  C[M,N] = A[M,K] @ W[N,K]^T (+ bias)
//   block 128x128, BK=16, 128 threads (4 warps 2x2, 64x64 per warp)
//   cp.async.cg double-buffered loads; ldmatrix fragments
// ---------------------------------------------------------------------------
#define GSTR 24

template <bool BIAS, bool HOUT>
__global__ __launch_bounds__(128)
void gemm_h(const __half* __restrict__ A, const __half* __restrict__ W,
            const float* __restrict__ bias, void* __restrict__ Cv,
            int Kn, int Nn)
{
    __shared__ __half Asm[2][128 * GSTR];
    __shared__ __half Wsm[2][128 * GSTR];

    const int t    = threadIdx.x;
    const int wid  = t >> 5;
    const int lid  = t & 31;
    const int gid  = lid >> 2;
    const int tg   = lid & 3;
    const int wm   = (wid >> 1) * 64;
    const int wn   = (wid & 1) * 64;
    const int row0 = blockIdx.y << 7;
    const int col0 = blockIdx.x << 7;

    const int mh = lid >> 3;
    const int rr = lid & 7;
    const uint32_t Asm_sh = (uint32_t)__cvta_generic_to_shared(&Asm[0][0]);
    const uint32_t Wsm_sh = (uint32_t)__cvta_generic_to_shared(&Wsm[0][0]);
    const uint32_t a_lane = ((mh & 1) * 8 + rr) * (GSTR * 2) + (mh >> 1) * 16;
    const uint32_t b_lane = ((mh >> 1) * 8 + rr) * (GSTR * 2) + (mh & 1) * 16;
    const uint32_t STAGE  = 128 * GSTR * 2;   // bytes per stage

    // loader: thread owns A row t and W row t (32B per kt each)
    const __half* Ap = A + (size_t)(row0 + t) * Kn;
    const __half* Wp = W + (size_t)(col0 + t) * Kn;
    const uint32_t aDst = Asm_sh + t * (GSTR * 2);
    const uint32_t wDst = Wsm_sh + t * (GSTR * 2);

    float acc[4][8][4];
#pragma unroll
    for (int i = 0; i < 4; i++)
#pragma unroll
        for (int j = 0; j < 8; j++)
#pragma unroll
            for (int r = 0; r < 4; r++) acc[i][j][r] = 0.0f;

    const int nkt = Kn >> 4;

    // preload stage 0 (async)
    cp16(aDst,      Ap);
    cp16(aDst + 16, Ap + 8);
    cp16(wDst,      Wp);
    cp16(wDst + 16, Wp + 8);
    CP_COMMIT();
    CP_WAIT0();
    __syncthreads();

    for (int kt = 0; kt < nkt; kt++) {
        const int cur = kt & 1, nxt = cur ^ 1;

        if (kt + 1 < nkt) {
            const __half* a = Ap + ((kt + 1) << 4);
            const __half* w = Wp + ((kt + 1) << 4);
            cp16(aDst + nxt * STAGE,      a);
            cp16(aDst + nxt * STAGE + 16, a + 8);
            cp16(wDst + nxt * STAGE,      w);
            cp16(wDst + nxt * STAGE + 16, w + 8);
            CP_COMMIT();
        }

        {
            const uint32_t abase = Asm_sh + cur * STAGE;
            const uint32_t bbase = Wsm_sh + cur * STAGE;
            uint32_t af[4][4], bf[8][2];
#pragma unroll
            for (int mt = 0; mt < 4; mt++)
                ldsm_x4(af[mt][0], af[mt][1], af[mt][2], af[mt][3],
                        abase + (wm + mt * 16) * (GSTR * 2) + a_lane);
#pragma unroll
            for (int p = 0; p < 4; p++)
                ldsm_x4(bf[2*p][0], bf[2*p][1], bf[2*p+1][0], bf[2*p+1][1],
                        bbase + (wn + p * 16) * (GSTR * 2) + b_lane);
#pragma unroll
            for (int mt = 0; mt < 4; mt++)
#pragma unroll
                for (int nt = 0; nt < 8; nt++)
                    mma_f16(acc[mt][nt][0], acc[mt][nt][1],
                            acc[mt][nt][2], acc[mt][nt][3],
                            af[mt][0], af[mt][1], af[mt][2], af[mt][3],
                            bf[nt][0], bf[nt][1]);
        }

        if (kt + 1 < nkt) CP_WAIT0();
        __syncthreads();
    }

#pragma unroll
    for (int mt = 0; mt < 4; mt++) {
        const int r = row0 + wm + mt * 16 + gid;
#pragma unroll
        for (int nt = 0; nt < 8; nt++) {
            const int c = col0 + wn + nt * 8 + tg * 2;
            if (HOUT) {
                __half* Ch = (__half*)Cv;
                *(uint32_t*)(Ch + (size_t)r * Nn + c) =
                    pack_h2(acc[mt][nt][0], acc[mt][nt][1]);
                *(uint32_t*)(Ch + (size_t)(r + 8) * Nn + c) =
                    pack_h2(acc[mt][nt][2], acc[mt][nt][3]);
            } else {
                float* Cf = (float*)Cv;
                float2 v0, v1;
                v0.x = acc[mt][nt][0]; v0.y = acc[mt][nt][1];
                v1.x = acc[mt][nt][2]; v1.y = acc[mt][nt][3];
                if (BIAS) {
                    float b0 = bias[c], b1 = bias[c + 1];
                    v0.x += b0; v0.y += b1;
                    v1.x += b0; v1.y += b1;
                }
                *(float2*)(Cf + (size_t)r * Nn + c)       = v0;
                *(float2*)(Cf + (size_t)(r + 8) * Nn + c) = v1;
            }
        }
    }
}

// ---------------------------------------------------------------------------
// Kernel 3: causal flash attention, fp16 MMA, fp32 softmax
//   double-buffered K/V via cp.async (overlap load j+1 with compute j)
//   Qs[128][72] Ps[128][72] Ks[2][64][72] Vs[2][64][72]
// ---------------------------------------------------------------------------
#define ASTR 72
#define KVSTAGE (64 * ASTR * 2)                         // bytes per KV stage
#define ATTN_SMEM_BYTES ((128 + 128 + 128 + 128) * ASTR * 2)   // 73728

__global__ __launch_bounds__(128)
void attn_h(const __half* __restrict__ qkv, __half* __restrict__ out)
{
    extern __shared__ __half smh[];
    __half* Qs  = smh;                     // [128][ASTR]
    __half* Ps  = Qs + 128 * ASTR;         // [128][ASTR]
    __half* Ks0 = Ps + 128 * ASTR;         // [2][64][ASTR]
    __half* Vs0 = Ks0 + 2 * 64 * ASTR;     // [2][64][ASTR]

    const int t   = threadIdx.x;
    const int w   = t >> 5;
    const int lid = t & 31;
    const int gid = lid >> 2;
    const int tg  = lid & 3;

    const int mh = lid >> 3;
    const int rr = lid & 7;
    const uint32_t Qs_sh = (uint32_t)__cvta_generic_to_shared(Qs);
    const uint32_t Ps_sh = (uint32_t)__cvta_generic_to_shared(Ps);
    const uint32_t Ks_sh = (uint32_t)__cvta_generic_to_shared(Ks0);
    const uint32_t Vs_sh = (uint32_t)__cvta_generic_to_shared(Vs0);
    const uint32_t a_lane = ((mh & 1) * 8 + rr) * (ASTR * 2) + (mh >> 1) * 16;  // A (Q/P)
    const uint32_t k_lane = ((mh >> 1) * 8 + rr) * (ASTR * 2) + (mh & 1) * 16;  // K B
    const uint32_t v_lane = ((mh & 1) * 8 + rr) * (ASTR * 2) + (mh >> 1) * 16;  // V B (trans)

    const int qi = (int)gridDim.x - 1 - (int)blockIdx.x;  // long blocks first
    const int bh = blockIdx.y;
    const int b  = bh >> 4;
    const int h  = bh & 15;

    const __half* qbase = qkv + (size_t)b * S_LEN * 3072 + h * 64;
    const __half* kbase = qbase + 1024;
    const __half* vbase = qbase + 2048;

    // load Q tile: 1 thread per row, 128B, scale by 0.125 (exact)
    {
        const __half* qp = qbase + (size_t)(qi * 128 + t) * 3072;
        __half* dst = &Qs[t * ASTR];
        const __half2 sc = __float2half2_rn(ATTN_SCALE);
#pragma unroll
        for (int jj = 0; jj < 8; jj++) {
            uint4 u = *(const uint4*)(qp + jj * 8);
            __half2* hp = (__half2*)&u;
            hp[0] = __hmul2(hp[0], sc); hp[1] = __hmul2(hp[1], sc);
            hp[2] = __hmul2(hp[2], sc); hp[3] = __hmul2(hp[3], sc);
            *(uint4*)(dst + jj * 8) = u;
        }
    }

    const int R0 = w * 32 + gid;
    float O[2][8][4];
    float rmax[2][2], rsum[2][2];
#pragma unroll
    for (int mt = 0; mt < 2; mt++) {
        rmax[mt][0] = -1e30f; rmax[mt][1] = -1e30f;
        rsum[mt][0] = 0.0f;   rsum[mt][1] = 0.0f;
#pragma unroll
        for (int nt = 0; nt < 8; nt++)
#pragma unroll
            for (int r = 0; r < 4; r++) O[mt][nt][r] = 0.0f;
    }

    // K/V loader: t<64 -> K row t ; t>=64 -> V row t-64 (128B per row via cp.async)
    const int kvrow = t & 63;
    const bool isV  = (t >= 64);
    const __half* kvsrc = (isV ? vbase : kbase) + (size_t)kvrow * 3072;
    const uint32_t kvDst = (isV ? Vs_sh : Ks_sh) + kvrow * (ASTR * 2);

    const int jmax = 2 * qi + 1;

    // preload tile 0 into stage 0
    {
        const __half* src = kvsrc;   // j=0
#pragma unroll
        for (int jj = 0; jj < 8; jj++)
            cp16(kvDst + jj * 16, src + jj * 8);
        CP_COMMIT();
        CP_WAIT0();
    }
    __syncthreads();   // KV tile 0 + Q ready

    for (int j = 0; j <= jmax; j++) {
        const int cur = j & 1, nxt = cur ^ 1;

        // prefetch tile j+1 into stage nxt
        if (j < jmax) {
            const __half* src = kvsrc + (size_t)(j + 1) * 64 * 3072;
            const uint32_t dst = kvDst + nxt * KVSTAGE;
#pragma unroll
            for (int jj = 0; jj < 8; jj++)
                cp16(dst + jj * 16, src + jj * 8);
            CP_COMMIT();
        }

        if (j * 64 <= qi * 128 + w * 32 + 31) {   // warp not fully masked
            const uint32_t kb_base = Ks_sh + cur * KVSTAGE;
            const uint32_t vb_base = Vs_sh + cur * KVSTAGE;

            // ---- S = Q @ K^T ----
            float sacc[2][8][4];
#pragma unroll
            for (int mt = 0; mt < 2; mt++)
#pragma unroll
                for (int nt = 0; nt < 8; nt++)
#pragma unroll
                    for (int r = 0; r < 4; r++) sacc[mt][nt][r] = 0.0f;

#pragma unroll
            for (int kk = 0; kk < 4; kk++) {
                uint32_t a[2][4], bk[8][2];
#pragma unroll
                for (int mt = 0; mt < 2; mt++)
                    ldsm_x4(a[mt][0], a[mt][1], a[mt][2], a[mt][3],
                            Qs_sh + (w * 32 + mt * 16) * (ASTR * 2) + kk * 32 + a_lane);
#pragma unroll
                for (int p = 0; p < 4; p++)
                    ldsm_x4(bk[2*p][0], bk[2*p][1], bk[2*p+1][0], bk[2*p+1][1],
                            kb_base + (p * 16) * (ASTR * 2) + kk * 32 + k_lane);
#pragma unroll
                for (int nt = 0; nt < 8; nt++) {
                    mma_f16(sacc[0][nt][0], sacc[0][nt][1], sacc[0][nt][2], sacc[0][nt][3],
                            a[0][0], a[0][1], a[0][2], a[0][3], bk[nt][0], bk[nt][1]);
                    mma_f16(sacc[1][nt][0], sacc[1][nt][1], sacc[1][nt][2], sacc[1][nt][3],
                            a[1][0], a[1][1], a[1][2], a[1][3], bk[nt][0], bk[nt][1]);
                }
            }

            // causal mask
            if (j * 64 + 63 > qi * 128 + w * 32) {
#pragma unroll
                for (int mt = 0; mt < 2; mt++) {
                    const int rg0 = qi * 128 + R0 + mt * 16;
                    const int rg1 = rg0 + 8;
#pragma unroll
                    for (int nt = 0; nt < 8; nt++) {
                        const int cg = j * 64 + nt * 8 + 2 * tg;
                        if (cg     > rg0) sacc[mt][nt][0] = -1e30f;
                        if (cg + 1 > rg0) sacc[mt][nt][1] = -1e30f;
                        if (cg     > rg1) sacc[mt][nt][2] = -1e30f;
                        if (cg + 1 > rg1) sacc[mt][nt][3] = -1e30f;
                    }
                }
            }

            // ---- online softmax ----
#pragma unroll
            for (int mt = 0; mt < 2; mt++)
#pragma unroll
                for (int hf = 0; hf < 2; hf++) {
                    const int i0 = hf * 2, i1 = hf * 2 + 1;
                    float m = -1e30f;
#pragma unroll
                    for (int nt = 0; nt < 8; nt++)
                        m = fmaxf(m, fmaxf(sacc[mt][nt][i0], sacc[mt][nt][i1]));
                    m = fmaxf(m, __shfl_xor_sync(0xffffffffu, m, 1));
                    m = fmaxf(m, __shfl_xor_sync(0xffffffffu, m, 2));

                    float nm = fmaxf(rmax[mt][hf], m);
                    float corr = __expf(rmax[mt][hf] - nm);
                    rmax[mt][hf] = nm;

                    const int prow = R0 + mt * 16 + hf * 8;
                    float ls = 0.0f;
#pragma unroll
                    for (int nt = 0; nt < 8; nt++) {
                        float p0 = __expf(sacc[mt][nt][i0] - nm);
                        float p1 = __expf(sacc[mt][nt][i1] - nm);
                        ls += p0 + p1;
                        *(uint32_t*)&Ps[prow * ASTR + nt * 8 + 2 * tg] = pack_h2(p0, p1);
                    }
                    ls += __shfl_xor_sync(0xffffffffu, ls, 1);
                    ls += __shfl_xor_sync(0xffffffffu, ls, 2);
                    rsum[mt][hf] = rsum[mt][hf] * corr + ls;

#pragma unroll
                    for (int nt = 0; nt < 8; nt++) {
                        O[mt][nt][i0] *= corr;
                        O[mt][nt][i1] *= corr;
                    }
                }
            __syncwarp();

            // ---- O += P @ V ----
#pragma unroll
            for (int kk = 0; kk < 4; kk++) {
                uint32_t a[2][4], bv[8][2];
#pragma unroll
                for (int mt = 0; mt < 2; mt++)
                    ldsm_x4(a[mt][0], a[mt][1], a[mt][2], a[mt][3],
                            Ps_sh + (w * 32 + mt * 16) * (ASTR * 2) + kk * 32 + a_lane);
#pragma unroll
                for (int p = 0; p < 4; p++)
                    ldsm_x4_t(bv[2*p][0], bv[2*p][1], bv[2*p+1][0], bv[2*p+1][1],
                              vb_base + (kk * 16) * (ASTR * 2) + p * 32 + v_lane);
#pragma unroll
                for (int nt = 0; nt < 8; nt++) {
                    mma_f16(O[0][nt][0], O[0][nt][1], O[0][nt][2], O[0][nt][3],
                            a[0][0], a[0][1], a[0][2], a[0][3], bv[nt][0], bv[nt][1]);
                    mma_f16(O[1][nt][0], O[1][nt][1], O[1][nt][2], O[1][nt][3],
                            a[1][0], a[1][1], a[1][2], a[1][3], bv[nt][0], bv[nt][1]);
                }
            }
        }

        if (j < jmax) CP_WAIT0();
        __syncthreads();
    }

    // epilogue: normalize + store half
    __half* obase = out + ((size_t)b * S_LEN + qi * 128) * 1024 + h * 64;
#pragma unroll
    for (int mt = 0; mt < 2; mt++) {
        const float inv0 = 1.0f / rsum[mt][0];
        const float inv1 = 1.0f / rsum[mt][1];
        const int r = R0 + mt * 16;
#pragma unroll
        for (int nt = 0; nt < 8; nt++) {
            const int c = nt * 8 + 2 * tg;
            *(uint32_t*)(obase + (size_t)r * 1024 + c) =
                pack_h2(O[mt][nt][0] * inv0, O[mt][nt][1] * inv0);
            *(uint32_t*)(obase + (size_t)(r + 8) * 1024 + c) =
                pack_h2(O[mt][nt][2] * inv1, O[mt][nt][3] * inv1);
        }
    }
}

// ---------------------------------------------------------------------------
// Launcher
// ---------------------------------------------------------------------------
extern "C" void kernel_launch(void* const* d_in, const int* in_sizes, int n_in,
                              void* d_out, int out_size)
{
    const float* x     = (const float*)d_in[0];
    // d_in[1] = mask: deterministic causal tril -> handled analytically
    const float* Wqkv  = (const float*)d_in[2];
    const float* Wproj = (const float*)d_in[3];
    const float* bproj = (const float*)d_in[4];
    const float* Aqkv  = (const float*)d_in[5];
    const float* Bqkv  = (const float*)d_in[6];
    const float* Aproj = (const float*)d_in[7];
    const float* Bproj = (const float*)d_in[8];

    __half *gx, *wq, *wp, *qkv, *att;
    cudaGetSymbolAddress((void**)&gx,  g_x);
    cudaGetSymbolAddress((void**)&wq,  g_Wqkv);
    cudaGetSymbolAddress((void**)&wp,  g_Wproj);
    cudaGetSymbolAddress((void**)&qkv, g_qkv);
    cudaGetSymbolAddress((void**)&att, g_att);

    cudaFuncSetAttribute(attn_h,
                         cudaFuncAttributeMaxDynamicSharedMemorySize, ATTN_SMEM_BYTES);

    // 0) x -> fp16
    const int n4 = M_TOK * E_DIM / 4;
    to_half<<<(n4 + 255) / 256, 256>>>((const float4*)x, (uint2*)gx, n4);

    // 1) fold LoRA into dense weights (fp16)
    fuse_w<<<(N_QKV * E_DIM + 255) / 256, 256>>>(Wqkv, Aqkv, Bqkv, wq, N_QKV);
    fuse_w<<<(E_DIM * E_DIM + 255) / 256, 256>>>(Wproj, Aproj, Bproj, wp, E_DIM);

    // 2) qkv = x @ Wqkv_eff^T   (fp16 TC, half output)
    gemm_h<false, true><<<dim3(N_QKV / 128, M_TOK / 128), 128>>>(
        gx, wq, nullptr, qkv, E_DIM, N_QKV);

    // 3) causal flash attention (fp16 TC, half output, cp.async pipelined)
    attn_h<<<dim3(S_LEN / 128, B_NUM * H_NUM), 128, ATTN_SMEM_BYTES>>>(qkv, att);

    // 4) out = att @ Wproj_eff^T + bproj   (fp16 TC, f32 output)
    gemm_h<true, false><<<dim3(E_DIM / 128, M_TOK / 128), 128>>>(
        att, wp, bproj, d_out, E_DIM, E_DIM);
}